// round 6
// baseline (speedup 1.0000x reference)
#include <cuda_runtime.h>
#include <cuda_bf16.h>

// ---------------------------------------------------------------------------
// SpMiddleFHDLite — sparse block1 + padded dense convs with adjacent-pair
// f32x2 packing, float4 tap loads (W-dims padded to %4 for LDG.128 alignment),
// COG=4 / NP=4 tiles.
// ---------------------------------------------------------------------------

#define EPS 1e-3f
typedef unsigned long long u64;

static constexpr int B_ = 2;

// W dims padded to multiple of 4 floats so every row start is 16B-aligned.
static constexpr int PD1 = 23, PH1 = 258, PW1 = 260;          // h1 + halo(1,1,1)
static constexpr long long PLANE1 = (long long)PD1 * PH1 * PW1;
static constexpr int PD2 = 11, PH2 = 130, PW2 = 132;          // h2 + halo(0,1,1)
static constexpr long long PLANE2 = (long long)PD2 * PH2 * PW2;
static constexpr long long PLANE3 = 5LL * 64 * 64;            // h3 (no halo)

__device__ __align__(256) float         g_h1[B_ * 16 * PLANE1];
__device__ __align__(256) unsigned char g_m1[B_ * PLANE1 + 16];
__device__ __align__(256) float         g_h2[B_ * 32 * PLANE2];
__device__ __align__(256) unsigned char g_m2[B_ * PLANE2 + 16];
__device__ __align__(256) float         g_h3[B_ * 64 * PLANE3];
__device__ __align__(256) unsigned char g_m3[B_ * PLANE3 + 16];

// ---------------------------------------------------------------------------
__device__ __forceinline__ u64 pk2(float lo, float hi) {
    u64 r;
    unsigned l = __float_as_uint(lo), h = __float_as_uint(hi);
    asm("mov.b64 %0, {%1,%2};" : "=l"(r) : "r"(l), "r"(h));
    return r;
}
__device__ __forceinline__ void upk2(u64 v, float& lo, float& hi) {
    unsigned l, h;
    asm("mov.b64 {%0,%1}, %2;" : "=r"(l), "=r"(h) : "l"(v));
    lo = __uint_as_float(l); hi = __uint_as_float(h);
}
__device__ __forceinline__ void fma2(u64& d, u64 a, u64 b) {
    asm("fma.rn.f32x2 %0, %1, %2, %0;" : "+l"(d) : "l"(a), "l"(b));
}

// ---------------------------------------------------------------------------
// Sparse block1: each thread = (voxel, co). Scatter w.f into h1 accumulator.
// ---------------------------------------------------------------------------
__global__ void __launch_bounds__(256)
scatter_conv1(const float* __restrict__ vf, const int* __restrict__ coors,
              float* __restrict__ h1, unsigned char* __restrict__ m1,
              const float* __restrict__ W, int nv) {
    __shared__ float sw[16 * 3 * 27];
    int tid = threadIdx.x;
    for (int i = tid; i < 16 * 3 * 27; i += 256) sw[i] = W[i];
    __syncthreads();

    int g = blockIdx.x * 256 + tid;
    int vi = g >> 4, co = g & 15;
    if (vi >= nv) return;

    float f0 = vf[3 * vi], f1 = vf[3 * vi + 1], f2 = vf[3 * vi + 2];
    int b = coors[4 * vi], z = coors[4 * vi + 1], y = coors[4 * vi + 2], x = coors[4 * vi + 3];

    int odl[2], kdl[2], nz = 1;
    if (z & 1) { odl[0] = (z - 1) >> 1; kdl[0] = 2; odl[1] = (z + 1) >> 1; kdl[1] = 0;
                 nz = (((z + 1) >> 1) < 21) ? 2 : 1; }
    else       { odl[0] = z >> 1; kdl[0] = 1; }
    int ohl[2], khl[2], ny = 1;
    if (y & 1) { ohl[0] = (y - 1) >> 1; khl[0] = 2; ohl[1] = (y + 1) >> 1; khl[1] = 0;
                 ny = (((y + 1) >> 1) < 256) ? 2 : 1; }
    else       { ohl[0] = y >> 1; khl[0] = 1; }
    int owl[2], kwl[2], nx = 1;
    if (x & 1) { owl[0] = (x - 1) >> 1; kwl[0] = 2; owl[1] = (x + 1) >> 1; kwl[1] = 0;
                 nx = (((x + 1) >> 1) < 256) ? 2 : 1; }
    else       { owl[0] = x >> 1; kwl[0] = 1; }

    const float* wc = &sw[co * 81];
    float* hc = h1 + (size_t)(b * 16 + co) * PLANE1;
    unsigned char* mb = m1 + (size_t)b * PLANE1;

    for (int iz = 0; iz < nz; iz++)
        for (int iy = 0; iy < ny; iy++)
            for (int ix = 0; ix < nx; ix++) {
                int k = (kdl[iz] * 3 + khl[iy]) * 3 + kwl[ix];
                float val = wc[k] * f0 + wc[27 + k] * f1 + wc[54 + k] * f2;
                size_t sp = (size_t)(odl[iz] + 1) * (PH1 * PW1)
                          + (size_t)(ohl[iy] + 1) * PW1 + (owl[ix] + 1);
                atomicAdd(hc + sp, val);
                if (co == 0) mb[sp] = 1;
            }
}

// ---------------------------------------------------------------------------
// BN+ReLU+mask elementwise pass, in place.
// ---------------------------------------------------------------------------
template<int CH, long long PLANE>
__global__ void __launch_bounds__(256)
bn_pass(float* __restrict__ h, const unsigned char* __restrict__ m,
        const float* __restrict__ Ga, const float* __restrict__ Be,
        const float* __restrict__ Rm, const float* __restrict__ Rv) {
    int c = blockIdx.y % CH;
    int b = blockIdx.y / CH;
    float inv = Ga[c] * rsqrtf(Rv[c] + EPS);
    float sh  = Be[c] - Rm[c] * inv;
    size_t p = ((size_t)blockIdx.x * 256 + threadIdx.x) * 4;
    if (p >= (size_t)PLANE) return;
    float4* vp = reinterpret_cast<float4*>(h + (size_t)blockIdx.y * PLANE + p);
    float4 v = *vp;
    uchar4 mm = *reinterpret_cast<const uchar4*>(m + (size_t)b * PLANE + p);
    v.x = mm.x ? fmaxf(fmaf(v.x, inv, sh), 0.f) : 0.f;
    v.y = mm.y ? fmaxf(fmaf(v.y, inv, sh), 0.f) : 0.f;
    v.z = mm.z ? fmaxf(fmaf(v.z, inv, sh), 0.f) : 0.f;
    v.w = mm.w ? fmaxf(fmaf(v.w, inv, sh), 0.f) : 0.f;
    *vp = v;
}

// ---------------------------------------------------------------------------
// Padded dense conv, adjacent-pair f32x2 packing.
// Lane handles output pairs (tp*64 + 2*lane, +1) for tp in [0,TP), rows
// oh0..oh0+TH-1, channels cg*COG..+COG.
// Path A (KW==3, SW==2): taps of a pair span 5 floats -> float4 + scalar.
//   Requires IWP % 4 == 0 (16B row alignment for LDG.128).
// Path B (KW==1, SW==1): taps of a pair = 2 floats -> float2.
// NSPLIT>1: raw partial sums via atomicAdd (bn applied by later bn_pass).
// ---------------------------------------------------------------------------
template<int CI, int CO, int COG, int TP, int TH, int BY, int NSPLIT,
         int IDP, int IHP, int IWP,
         int OD, int OH, int OW,
         int OPD, int OPH, int OPW,
         int KD, int KH, int KW, int SD, int SH, int SW, int OWPAD>
__global__ void __launch_bounds__(32 * BY, 3)
conv_pad(const float* __restrict__ in, const unsigned char* __restrict__ mi,
         float* __restrict__ out, unsigned char* __restrict__ mo,
         const float* __restrict__ Wt, const float* __restrict__ Ga,
         const float* __restrict__ Be, const float* __restrict__ Rm,
         const float* __restrict__ Rv) {
    constexpr int NCOG = CO / COG;
    constexpr int NP = TP * TH;          // packed accumulators (1 per pair)
    constexpr int NT = 2 * NP;           // outputs
    constexpr int NTHR = 32 * BY;
    constexpr int CIL = CI / NSPLIT;
    constexpr int WSTEPS = CIL * KD * KH * KW;
    constexpr int ODP = OD + 2 * OPD, OHP = OH + 2 * OPH;
    constexpr int OWP = OW + 2 * OPW + OWPAD;   // physical padded out width
    constexpr bool PATH_A = (KW == 3 && SW == 2);
    static_assert(!PATH_A || (IWP % 4 == 0), "float4 path needs IWP%4==0");
    extern __shared__ u64 sw2[];

    const int lane = threadIdx.x;
    const int tid = threadIdx.y * 32 + lane;
    int zi = blockIdx.z;
    const int cg = zi % NCOG; zi /= NCOG;
    const int od = zi % OD;  zi /= OD;
    const int b  = zi % B_;
    const int sp = zi / B_;
    const int ci0 = sp * CIL;

    for (int i = tid; i < WSTEPS * COG; i += NTHR) {
        int co = i % COG; int r = i / COG;
        int kw = r % KW; r /= KW;
        int kh = r % KH; r /= KH;
        int kd = r % KD; int cil = r / KD;
        float w = Wt[((((cg * COG + co) * CI + ci0 + cil) * KD + kd) * KH + kh) * KW + kw];
        sw2[i] = pk2(w, w);
    }
    __syncthreads();

    const int oh0 = (blockIdx.y * BY + threadIdx.y) * TH;

    // mask = OR of input mask over window, per output
    unsigned any[NT];
#pragma unroll
    for (int t = 0; t < NT; t++) any[t] = 0;
    if (NSPLIT == 1 || (cg == 0 && sp == 0)) {
        const unsigned char* mb = mi + (size_t)b * IDP * IHP * IWP;
#pragma unroll
        for (int kd = 0; kd < KD; kd++)
#pragma unroll
            for (int kh = 0; kh < KH; kh++)
#pragma unroll
                for (int th = 0; th < TH; th++) {
                    const unsigned char* mrow =
                        mb + ((size_t)(od * SD + kd) * IHP + (oh0 + th) * SH + kh) * IWP;
#pragma unroll
                    for (int tp = 0; tp < TP; tp++) {
                        int owA = tp * 64 + 2 * lane;
#pragma unroll
                        for (int kw = 0; kw < KW; kw++) {
                            any[(th * TP + tp) * 2 + 0] |= mrow[owA * SW + kw];
                            any[(th * TP + tp) * 2 + 1] |= mrow[(owA + 1) * SW + kw];
                        }
                    }
                }
    }

    u64 acc[COG][NP];
#pragma unroll
    for (int co = 0; co < COG; co++)
#pragma unroll
        for (int p = 0; p < NP; p++) acc[co][p] = 0ull;

    const float* inb = in + ((size_t)b * CI + ci0) * IDP * IHP * IWP;
#pragma unroll 1
    for (int cil = 0; cil < CIL; cil++) {
#pragma unroll
        for (int kd = 0; kd < KD; kd++) {
            const float* pl = inb + ((size_t)cil * IDP + od * SD + kd) * (IHP * IWP);
#pragma unroll
            for (int kh = 0; kh < KH; kh++) {
                const float* row[TH];
#pragma unroll
                for (int th = 0; th < TH; th++)
                    row[th] = pl + ((size_t)(oh0 + th) * SH + kh) * IWP;

                if (PATH_A) {
                    float4 q[NP]; float s[NP];
#pragma unroll
                    for (int th = 0; th < TH; th++)
#pragma unroll
                        for (int tp = 0; tp < TP; tp++) {
                            int iw = tp * 128 + 4 * lane;     // = 2*owA, 16B aligned
                            q[th * TP + tp] =
                                *reinterpret_cast<const float4*>(row[th] + iw);
                            s[th * TP + tp] = row[th][iw + 4];
                        }
#pragma unroll
                    for (int kw = 0; kw < 3; kw++) {
                        u64 vp[NP];
#pragma unroll
                        for (int p = 0; p < NP; p++) {
                            float4 qq = q[p];
                            float vA = (kw == 0) ? qq.x : (kw == 1) ? qq.y : qq.z;
                            float vB = (kw == 0) ? qq.z : (kw == 1) ? qq.w : s[p];
                            vp[p] = pk2(vA, vB);
                        }
                        const u64* wp = &sw2[(((cil * KD + kd) * KH + kh) * 3 + kw) * COG];
#pragma unroll
                        for (int co = 0; co < COG; co++) {
                            u64 w2 = wp[co];
#pragma unroll
                            for (int p = 0; p < NP; p++) fma2(acc[co][p], vp[p], w2);
                        }
                    }
                } else {
                    // KW==1 && SW==1
                    u64 vp[NP];
#pragma unroll
                    for (int th = 0; th < TH; th++)
#pragma unroll
                        for (int tp = 0; tp < TP; tp++) {
                            int iw = tp * 64 + 2 * lane;
                            float2 f = *reinterpret_cast<const float2*>(row[th] + iw);
                            vp[th * TP + tp] = pk2(f.x, f.y);
                        }
                    const u64* wp = &sw2[((cil * KD + kd) * KH + kh) * COG];
#pragma unroll
                    for (int co = 0; co < COG; co++) {
                        u64 w2 = wp[co];
#pragma unroll
                        for (int p = 0; p < NP; p++) fma2(acc[co][p], vp[p], w2);
                    }
                }
            }
        }
    }

    // epilogue
    if (NSPLIT > 1) {
#pragma unroll
        for (int co = 0; co < COG; co++) {
            int c = cg * COG + co;
            size_t obc = ((size_t)(b * CO + c) * ODP + od) * ((size_t)OHP * OWP);
#pragma unroll
            for (int p = 0; p < NP; p++) {
                float a0, a1;
                upk2(acc[co][p], a0, a1);
                int th = p / TP, tp = p % TP;
                int owA = tp * 64 + 2 * lane;
                atomicAdd(&out[obc + (size_t)(oh0 + th) * OWP + owA], a0);
                atomicAdd(&out[obc + (size_t)(oh0 + th) * OWP + owA + 1], a1);
            }
        }
        if (cg == 0 && sp == 0) {
            size_t mbc = ((size_t)b * ODP + od) * ((size_t)OHP * OWP);
#pragma unroll
            for (int p = 0; p < NP; p++) {
                int th = p / TP, tp = p % TP;
                int owA = tp * 64 + 2 * lane;
                mo[mbc + (size_t)(oh0 + th) * OWP + owA]     = any[2 * p + 0] ? 1 : 0;
                mo[mbc + (size_t)(oh0 + th) * OWP + owA + 1] = any[2 * p + 1] ? 1 : 0;
            }
        }
    } else {
#pragma unroll
        for (int co = 0; co < COG; co++) {
            int c = cg * COG + co;
            float inv = Ga[c] * rsqrtf(Rv[c] + EPS);
            float sh  = Be[c] - Rm[c] * inv;
            size_t obc = ((size_t)(b * CO + c) * ODP + od + OPD) * ((size_t)OHP * OWP);
#pragma unroll
            for (int p = 0; p < NP; p++) {
                float a0, a1;
                upk2(acc[co][p], a0, a1);
                int th = p / TP, tp = p % TP;
                int owA = tp * 64 + 2 * lane;
                float v0 = any[2 * p + 0] ? fmaxf(fmaf(a0, inv, sh), 0.f) : 0.f;
                float v1 = any[2 * p + 1] ? fmaxf(fmaf(a1, inv, sh), 0.f) : 0.f;
                size_t o = obc + (size_t)(oh0 + th + OPH) * OWP + owA + OPW;
                out[o]     = v0;
                out[o + 1] = v1;
            }
        }
        if (cg == 0) {
            size_t mbc = ((size_t)b * ODP + od + OPD) * ((size_t)OHP * OWP);
#pragma unroll
            for (int p = 0; p < NP; p++) {
                int th = p / TP, tp = p % TP;
                int owA = tp * 64 + 2 * lane;
                size_t o = mbc + (size_t)(oh0 + th + OPH) * OWP + owA + OPW;
                mo[o]     = any[2 * p + 0] ? 1 : 0;
                mo[o + 1] = any[2 * p + 1] ? 1 : 0;
            }
        }
    }
}

// ---------------------------------------------------------------------------
extern "C" void kernel_launch(void* const* d_in, const int* in_sizes, int n_in,
                              void* d_out, int out_size) {
    const float* vf    = (const float*)d_in[0];
    const int*   coors = (const int*)d_in[1];
    const float *w1 = (const float*)d_in[3],  *gg1 = (const float*)d_in[4],
                *b1 = (const float*)d_in[5],  *rm1 = (const float*)d_in[6],
                *rv1 = (const float*)d_in[7];
    const float *w2 = (const float*)d_in[8],  *gg2 = (const float*)d_in[9],
                *b2 = (const float*)d_in[10], *rm2 = (const float*)d_in[11],
                *rv2 = (const float*)d_in[12];
    const float *w3 = (const float*)d_in[13], *gg3 = (const float*)d_in[14],
                *b3 = (const float*)d_in[15], *rm3 = (const float*)d_in[16],
                *rv3 = (const float*)d_in[17];
    const float *w4 = (const float*)d_in[18], *gg4 = (const float*)d_in[19],
                *b4 = (const float*)d_in[20], *rm4 = (const float*)d_in[21],
                *rv4 = (const float*)d_in[22];
    float* out = (float*)d_out;
    const int nv = in_sizes[0] / 3;

    float *h1, *h2, *h3;
    unsigned char *m1, *m2, *m3;
    cudaGetSymbolAddress((void**)&h1, g_h1);
    cudaGetSymbolAddress((void**)&m1, g_m1);
    cudaGetSymbolAddress((void**)&h2, g_h2);
    cudaGetSymbolAddress((void**)&m2, g_m2);
    cudaGetSymbolAddress((void**)&h3, g_h3);
    cudaGetSymbolAddress((void**)&m3, g_m3);

    cudaMemsetAsync(h1, 0, (size_t)B_ * 16 * PLANE1 * sizeof(float));
    cudaMemsetAsync(m1, 0, (size_t)B_ * PLANE1 + 16);
    cudaMemsetAsync(h2, 0, (size_t)B_ * 32 * PLANE2 * sizeof(float));
    cudaMemsetAsync(m2, 0, (size_t)B_ * PLANE2 + 16);
    cudaMemsetAsync(h3, 0, (size_t)B_ * 64 * PLANE3 * sizeof(float));

    // block1 sparse
    {
        int nthreads = nv * 16;
        scatter_conv1<<<(nthreads + 255) / 256, 256>>>(vf, coors, h1, m1, w1, nv);
        dim3 grid((unsigned)((PLANE1 / 4 + 255) / 256), B_ * 16);
        bn_pass<16, PLANE1><<<grid, 256>>>(h1, m1, gg1, b1, rm1, rv1);
    }

    dim3 blk(32, 8, 1);

    // block2: 16->32, (23,258,260)pad -> (11,128,128), out halo (0,1,1)+pad2
    // COG=4, TP=2, TH=2 (NP=4). 1408 blocks, 8 warps each
    {
        auto k = conv_pad<16, 32, 4, 2, 2, 8, 1, 23, 258, 260, 11, 128, 128,
                          0, 1, 1, 3, 3, 3, 2, 2, 2, 2>;
        size_t smem = (16ull * 27) * 4 * 8;  // 13824
        dim3 grid(1, 8, B_ * 11 * 8);
        k<<<grid, blk, smem>>>(h1, m1, h2, m2, w2, gg2, b2, rm2, rv2);
    }
    // block3: 32->64, (11,130,132)pad -> (5,64,64) raw, CI split x2
    // COG=4, TP=1, TH=4 (NP=4). 640 blocks
    {
        auto k = conv_pad<32, 64, 4, 1, 4, 8, 2, 11, 130, 132, 5, 64, 64,
                          0, 0, 0, 3, 3, 3, 2, 2, 2, 0>;
        size_t smem = (16ull * 27) * 4 * 8;  // 13824
        dim3 grid(1, 2, 16 * 5 * B_ * 2);
        k<<<grid, blk, smem>>>(h2, m2, h3, m3, w3, gg3, b3, rm3, rv3);
        dim3 bgrid((unsigned)((PLANE3 / 4 + 255) / 256), B_ * 64);
        bn_pass<64, PLANE3><<<bgrid, 256>>>(h3, m3, gg3, b3, rm3, rv3);
    }
    // block4: 64->64, k(3,1,1) s(2,1,1), (5,64,64) -> (2,64,64) = d_out
    {
        auto k = conv_pad<64, 64, 4, 1, 4, 8, 1, 5, 64, 64, 2, 64, 64,
                          0, 0, 0, 3, 1, 1, 2, 1, 1, 0>;
        size_t smem = (64ull * 3) * 4 * 8;   // 6144
        dim3 grid(1, 2, 16 * 2 * B_);
        k<<<grid, blk, smem>>>(h3, m3, out, m3, w4, gg4, b4, rm4, rv4);
    }
}

// round 8
// speedup vs baseline: 1.0366x; 1.0366x over previous
#include <cuda_runtime.h>
#include <cuda_bf16.h>

// ---------------------------------------------------------------------------
// SpMiddleFHDLite — sparse block1 + padded dense convs, packed fma.rn.f32x2,
// R4 code shape (non-adjacent pairing, float2 kw-overlap loads), NP=4 tiles.
// ---------------------------------------------------------------------------

#define EPS 1e-3f
typedef unsigned long long u64;

static constexpr int B_ = 2;

// h1 padded for block2's pad (1,1,1): (23,258,258)
static constexpr int PD1 = 23, PH1 = 258, PW1 = 258;
static constexpr long long PLANE1 = (long long)PD1 * PH1 * PW1;
// h2 padded for block3's pad (0,1,1): (11,130,130)
static constexpr int PD2 = 11, PH2 = 130, PW2 = 130;
static constexpr long long PLANE2 = (long long)PD2 * PH2 * PW2;
static constexpr long long PLANE3 = 5LL * 64 * 64;   // h3 (no halo)

__device__ __align__(256) float         g_h1[B_ * 16 * PLANE1];
__device__ __align__(256) unsigned char g_m1[B_ * PLANE1 + 16];
__device__ __align__(256) float         g_h2[B_ * 32 * PLANE2];
__device__ __align__(256) unsigned char g_m2[B_ * PLANE2 + 16];
__device__ __align__(256) float         g_h3[B_ * 64 * PLANE3];
__device__ __align__(256) unsigned char g_m3[B_ * PLANE3 + 16];

// ---------------------------------------------------------------------------
__device__ __forceinline__ u64 pk2(float lo, float hi) {
    u64 r;
    unsigned l = __float_as_uint(lo), h = __float_as_uint(hi);
    asm("mov.b64 %0, {%1,%2};" : "=l"(r) : "r"(l), "r"(h));
    return r;
}
__device__ __forceinline__ void upk2(u64 v, float& lo, float& hi) {
    unsigned l, h;
    asm("mov.b64 {%0,%1}, %2;" : "=r"(l), "=r"(h) : "l"(v));
    lo = __uint_as_float(l); hi = __uint_as_float(h);
}
__device__ __forceinline__ void fma2(u64& d, u64 a, u64 b) {
    asm("fma.rn.f32x2 %0, %1, %2, %0;" : "+l"(d) : "l"(a), "l"(b));
}

// ---------------------------------------------------------------------------
// Sparse block1: each thread = (voxel, co). Scatter w.f into h1 accumulator.
// ---------------------------------------------------------------------------
__global__ void __launch_bounds__(256)
scatter_conv1(const float* __restrict__ vf, const int* __restrict__ coors,
              float* __restrict__ h1, unsigned char* __restrict__ m1,
              const float* __restrict__ W, int nv) {
    __shared__ float sw[16 * 3 * 27];
    int tid = threadIdx.x;
    for (int i = tid; i < 16 * 3 * 27; i += 256) sw[i] = W[i];
    __syncthreads();

    int g = blockIdx.x * 256 + tid;
    int vi = g >> 4, co = g & 15;
    if (vi >= nv) return;

    float f0 = vf[3 * vi], f1 = vf[3 * vi + 1], f2 = vf[3 * vi + 2];
    int4 cz = *reinterpret_cast<const int4*>(coors + 4 * vi);
    int b = cz.x, z = cz.y, y = cz.z, x = cz.w;

    int odl[2], kdl[2], nz = 1;
    if (z & 1) { odl[0] = (z - 1) >> 1; kdl[0] = 2; odl[1] = (z + 1) >> 1; kdl[1] = 0;
                 nz = (((z + 1) >> 1) < 21) ? 2 : 1; }
    else       { odl[0] = z >> 1; kdl[0] = 1; }
    int ohl[2], khl[2], ny = 1;
    if (y & 1) { ohl[0] = (y - 1) >> 1; khl[0] = 2; ohl[1] = (y + 1) >> 1; khl[1] = 0;
                 ny = (((y + 1) >> 1) < 256) ? 2 : 1; }
    else       { ohl[0] = y >> 1; khl[0] = 1; }
    int owl[2], kwl[2], nx = 1;
    if (x & 1) { owl[0] = (x - 1) >> 1; kwl[0] = 2; owl[1] = (x + 1) >> 1; kwl[1] = 0;
                 nx = (((x + 1) >> 1) < 256) ? 2 : 1; }
    else       { owl[0] = x >> 1; kwl[0] = 1; }

    const float* wc = &sw[co * 81];
    float* hc = h1 + (size_t)(b * 16 + co) * PLANE1;
    unsigned char* mb = m1 + (size_t)b * PLANE1;

    for (int iz = 0; iz < nz; iz++)
        for (int iy = 0; iy < ny; iy++)
            for (int ix = 0; ix < nx; ix++) {
                int k = (kdl[iz] * 3 + khl[iy]) * 3 + kwl[ix];
                float val = wc[k] * f0 + wc[27 + k] * f1 + wc[54 + k] * f2;
                size_t sp = (size_t)(odl[iz] + 1) * (PH1 * PW1)
                          + (size_t)(ohl[iy] + 1) * PW1 + (owl[ix] + 1);
                atomicAdd(hc + sp, val);
                if (co == 0) mb[sp] = 1;
            }
}

// ---------------------------------------------------------------------------
// BN+ReLU+mask elementwise pass, in place.
// ---------------------------------------------------------------------------
template<int CH, long long PLANE>
__global__ void __launch_bounds__(256)
bn_pass(float* __restrict__ h, const unsigned char* __restrict__ m,
        const float* __restrict__ Ga, const float* __restrict__ Be,
        const float* __restrict__ Rm, const float* __restrict__ Rv) {
    int c = blockIdx.y % CH;
    int b = blockIdx.y / CH;
    float inv = Ga[c] * rsqrtf(Rv[c] + EPS);
    float sh  = Be[c] - Rm[c] * inv;
    size_t p = ((size_t)blockIdx.x * 256 + threadIdx.x) * 4;
    if (p >= (size_t)PLANE) return;
    float4* vp = reinterpret_cast<float4*>(h + (size_t)blockIdx.y * PLANE + p);
    float4 v = *vp;
    uchar4 mm = *reinterpret_cast<const uchar4*>(m + (size_t)b * PLANE + p);
    v.x = mm.x ? fmaxf(fmaf(v.x, inv, sh), 0.f) : 0.f;
    v.y = mm.y ? fmaxf(fmaf(v.y, inv, sh), 0.f) : 0.f;
    v.z = mm.z ? fmaxf(fmaf(v.z, inv, sh), 0.f) : 0.f;
    v.w = mm.w ? fmaxf(fmaf(v.w, inv, sh), 0.f) : 0.f;
    *vp = v;
}

// ---------------------------------------------------------------------------
// Padded dense conv (+ optional fused BN/ReLU/mask), packed f32x2 FMA.
// 32*TW == OW. Thread tile: TW x TH outputs x COG channels.
// NSPLIT>1: raw partial sums via atomicAdd (bn applied by later bn_pass).
// KW==3 && SW==2: kw0/kw1 taps share one float2 load.
// ---------------------------------------------------------------------------
template<int CI, int CO, int COG, int TW, int TH, int BY, int NSPLIT,
         int IDP, int IHP, int IWP,
         int OD, int OH, int OW,
         int OPD, int OPH, int OPW,
         int KD, int KH, int KW, int SD, int SH, int SW>
__global__ void __launch_bounds__(32 * BY)
conv_pad(const float* __restrict__ in, const unsigned char* __restrict__ mi,
         float* __restrict__ out, unsigned char* __restrict__ mo,
         const float* __restrict__ Wt, const float* __restrict__ Ga,
         const float* __restrict__ Be, const float* __restrict__ Rm,
         const float* __restrict__ Rv) {
    constexpr int NCOG = CO / COG;
    constexpr int NT = TW * TH;      // even
    constexpr int NP = NT / 2;
    constexpr int NTHR = 32 * BY;
    constexpr int CIL = CI / NSPLIT;
    constexpr int WSTEPS = CIL * KD * KH * KW;
    constexpr int ODP = OD + 2 * OPD, OHP = OH + 2 * OPH, OWP = OW + 2 * OPW;
    constexpr bool KW3S2 = (KW == 3 && SW == 2);
    extern __shared__ u64 sw2[];

    const int tid = threadIdx.y * 32 + threadIdx.x;
    int zi = blockIdx.z;
    const int cg = zi % NCOG; zi /= NCOG;
    const int od = zi % OD;  zi /= OD;
    const int b  = zi % B_;
    const int sp = zi / B_;          // ci split index
    const int ci0 = sp * CIL;

    for (int i = tid; i < WSTEPS * COG; i += NTHR) {
        int co = i % COG; int r = i / COG;
        int kw = r % KW; r /= KW;
        int kh = r % KH; r /= KH;
        int kd = r % KD; int cil = r / KD;
        float w = Wt[((((cg * COG + co) * CI + ci0 + cil) * KD + kd) * KH + kh) * KW + kw];
        sw2[i] = pk2(w, w);
    }
    __syncthreads();

    const int ow0 = threadIdx.x;                           // + 32*tw
    const int oh0 = (blockIdx.y * BY + threadIdx.y) * TH;  // + th

    unsigned any[NT];
#pragma unroll
    for (int t = 0; t < NT; t++) any[t] = 0;
    if (NSPLIT == 1 || (cg == 0 && sp == 0)) {
        const unsigned char* mb = mi + (size_t)b * IDP * IHP * IWP;
#pragma unroll
        for (int kd = 0; kd < KD; kd++)
#pragma unroll
            for (int kh = 0; kh < KH; kh++)
#pragma unroll
                for (int th = 0; th < TH; th++) {
                    const unsigned char* mrow =
                        mb + ((size_t)(od * SD + kd) * IHP + (oh0 + th) * SH + kh) * IWP;
#pragma unroll
                    for (int kw = 0; kw < KW; kw++)
#pragma unroll
                        for (int tw = 0; tw < TW; tw++)
                            any[th * TW + tw] |= mrow[(ow0 + 32 * tw) * SW + kw];
                }
    }

    u64 acc[COG][NP];
#pragma unroll
    for (int co = 0; co < COG; co++)
#pragma unroll
        for (int p = 0; p < NP; p++) acc[co][p] = 0ull;

    const float* inb = in + ((size_t)b * CI + ci0) * IDP * IHP * IWP;
#pragma unroll 1
    for (int cil = 0; cil < CIL; cil++) {
#pragma unroll
        for (int kd = 0; kd < KD; kd++) {
            const float* pl = inb + ((size_t)cil * IDP + od * SD + kd) * (IHP * IWP);
#pragma unroll
            for (int kh = 0; kh < KH; kh++) {
                const float* row[TH];
#pragma unroll
                for (int th = 0; th < TH; th++)
                    row[th] = pl + ((size_t)(oh0 + th) * SH + kh) * IWP;

                if (KW3S2) {
                    float2 a01[NT]; float a2[NT];
#pragma unroll
                    for (int th = 0; th < TH; th++)
#pragma unroll
                        for (int tw = 0; tw < TW; tw++) {
                            int iw = (ow0 + 32 * tw) * 2;
                            a01[th * TW + tw] =
                                *reinterpret_cast<const float2*>(row[th] + iw);
                            a2[th * TW + tw] = row[th][iw + 2];
                        }
#pragma unroll
                    for (int kw = 0; kw < 3; kw++) {
                        u64 vp[NP];
#pragma unroll
                        for (int p = 0; p < NP; p++) {
                            int t0 = 2 * p, t1 = 2 * p + 1;
                            float v0 = (kw == 0) ? a01[t0].x : (kw == 1) ? a01[t0].y : a2[t0];
                            float v1 = (kw == 0) ? a01[t1].x : (kw == 1) ? a01[t1].y : a2[t1];
                            vp[p] = pk2(v0, v1);
                        }
                        const u64* wp = &sw2[(((cil * KD + kd) * KH + kh) * 3 + kw) * COG];
#pragma unroll
                        for (int co = 0; co < COG; co++) {
                            u64 w2 = wp[co];
#pragma unroll
                            for (int p = 0; p < NP; p++) fma2(acc[co][p], vp[p], w2);
                        }
                    }
                } else {
#pragma unroll
                    for (int kw = 0; kw < KW; kw++) {
                        u64 vp[NP];
#pragma unroll
                        for (int p = 0; p < NP; p++) {
                            int t0 = 2 * p, t1 = 2 * p + 1;
                            int th0 = t0 / TW, tw0 = t0 % TW;
                            int th1 = t1 / TW, tw1 = t1 % TW;
                            float v0 = row[th0][(ow0 + 32 * tw0) * SW + kw];
                            float v1 = row[th1][(ow0 + 32 * tw1) * SW + kw];
                            vp[p] = pk2(v0, v1);
                        }
                        const u64* wp = &sw2[(((cil * KD + kd) * KH + kh) * KW + kw) * COG];
#pragma unroll
                        for (int co = 0; co < COG; co++) {
                            u64 w2 = wp[co];
#pragma unroll
                            for (int p = 0; p < NP; p++) fma2(acc[co][p], vp[p], w2);
                        }
                    }
                }
            }
        }
    }

    if (NSPLIT > 1) {
#pragma unroll
        for (int co = 0; co < COG; co++) {
            int c = cg * COG + co;
            size_t obc = ((size_t)(b * CO + c) * ODP + od) * ((size_t)OHP * OWP);
#pragma unroll
            for (int p = 0; p < NP; p++) {
                float a0, a1;
                upk2(acc[co][p], a0, a1);
                int t0 = 2 * p, t1 = 2 * p + 1;
                int th0 = t0 / TW, tw0 = t0 % TW;
                int th1 = t1 / TW, tw1 = t1 % TW;
                atomicAdd(&out[obc + (size_t)(oh0 + th0) * OWP + (ow0 + 32 * tw0)], a0);
                atomicAdd(&out[obc + (size_t)(oh0 + th1) * OWP + (ow0 + 32 * tw1)], a1);
            }
        }
        if (cg == 0 && sp == 0) {
            size_t mbc = ((size_t)b * ODP + od) * ((size_t)OHP * OWP);
#pragma unroll
            for (int t = 0; t < NT; t++) {
                int th = t / TW, tw = t % TW;
                mo[mbc + (size_t)(oh0 + th) * OWP + (ow0 + 32 * tw)] = any[t] ? 1 : 0;
            }
        }
    } else {
#pragma unroll
        for (int co = 0; co < COG; co++) {
            int c = cg * COG + co;
            float inv = Ga[c] * rsqrtf(Rv[c] + EPS);
            float sh  = Be[c] - Rm[c] * inv;
            size_t obc = ((size_t)(b * CO + c) * ODP + od + OPD) * ((size_t)OHP * OWP);
#pragma unroll
            for (int p = 0; p < NP; p++) {
                float a0, a1;
                upk2(acc[co][p], a0, a1);
                int t0 = 2 * p, t1 = 2 * p + 1;
                int th0 = t0 / TW, tw0 = t0 % TW;
                int th1 = t1 / TW, tw1 = t1 % TW;
                float v0 = any[t0] ? fmaxf(fmaf(a0, inv, sh), 0.f) : 0.f;
                float v1 = any[t1] ? fmaxf(fmaf(a1, inv, sh), 0.f) : 0.f;
                out[obc + (size_t)(oh0 + th0 + OPH) * OWP + (ow0 + 32 * tw0 + OPW)] = v0;
                out[obc + (size_t)(oh0 + th1 + OPH) * OWP + (ow0 + 32 * tw1 + OPW)] = v1;
            }
        }
        if (cg == 0) {
            size_t mbc = ((size_t)b * ODP + od + OPD) * ((size_t)OHP * OWP);
#pragma unroll
            for (int t = 0; t < NT; t++) {
                int th = t / TW, tw = t % TW;
                mo[mbc + (size_t)(oh0 + th + OPH) * OWP + (ow0 + 32 * tw + OPW)] = any[t] ? 1 : 0;
            }
        }
    }
}

// ---------------------------------------------------------------------------
extern "C" void kernel_launch(void* const* d_in, const int* in_sizes, int n_in,
                              void* d_out, int out_size) {
    const float* vf    = (const float*)d_in[0];
    const int*   coors = (const int*)d_in[1];
    const float *w1 = (const float*)d_in[3],  *gg1 = (const float*)d_in[4],
                *b1 = (const float*)d_in[5],  *rm1 = (const float*)d_in[6],
                *rv1 = (const float*)d_in[7];
    const float *w2 = (const float*)d_in[8],  *gg2 = (const float*)d_in[9],
                *b2 = (const float*)d_in[10], *rm2 = (const float*)d_in[11],
                *rv2 = (const float*)d_in[12];
    const float *w3 = (const float*)d_in[13], *gg3 = (const float*)d_in[14],
                *b3 = (const float*)d_in[15], *rm3 = (const float*)d_in[16],
                *rv3 = (const float*)d_in[17];
    const float *w4 = (const float*)d_in[18], *gg4 = (const float*)d_in[19],
                *b4 = (const float*)d_in[20], *rm4 = (const float*)d_in[21],
                *rv4 = (const float*)d_in[22];
    float* out = (float*)d_out;
    const int nv = in_sizes[0] / 3;

    float *h1, *h2, *h3;
    unsigned char *m1, *m2, *m3;
    cudaGetSymbolAddress((void**)&h1, g_h1);
    cudaGetSymbolAddress((void**)&m1, g_m1);
    cudaGetSymbolAddress((void**)&h2, g_h2);
    cudaGetSymbolAddress((void**)&m2, g_m2);
    cudaGetSymbolAddress((void**)&h3, g_h3);
    cudaGetSymbolAddress((void**)&m3, g_m3);

    cudaMemsetAsync(h1, 0, (size_t)B_ * 16 * PLANE1 * sizeof(float));
    cudaMemsetAsync(m1, 0, (size_t)B_ * PLANE1 + 16);
    cudaMemsetAsync(h2, 0, (size_t)B_ * 32 * PLANE2 * sizeof(float));
    cudaMemsetAsync(m2, 0, (size_t)B_ * PLANE2 + 16);
    cudaMemsetAsync(h3, 0, (size_t)B_ * 64 * PLANE3 * sizeof(float));

    // block1 sparse
    {
        int nthreads = nv * 16;
        scatter_conv1<<<(nthreads + 255) / 256, 256>>>(vf, coors, h1, m1, w1, nv);
        dim3 grid((unsigned)((PLANE1 / 4 + 255) / 256), B_ * 16);
        bn_pass<16, PLANE1><<<grid, 256>>>(h1, m1, gg1, b1, rm1, rv1);
    }

    dim3 blk(32, 8, 1);

    // block2: 16->32, (23,258,258)pad -> (11,128,128), out halo (0,1,1)
    // COG=8, TW=4, TH=2 (NP=4). grid: y=8, z=4*11*2=88 -> 704 blocks
    {
        auto k = conv_pad<16, 32, 8, 4, 2, 8, 1, 23, 258, 258, 11, 128, 128,
                          0, 1, 1, 3, 3, 3, 2, 2, 2>;
        size_t smem = (16ull * 27) * 8 * 8;  // 27648
        dim3 grid(1, 8, B_ * 11 * 4);
        k<<<grid, blk, smem>>>(h1, m1, h2, m2, w2, gg2, b2, rm2, rv2);
    }
    // block3: 32->64, (11,130,130)pad -> (5,64,64) raw, CI split x2
    // COG=8, TW=2, TH=4 (NP=4). grid: y=2, z=8*5*2*2=160 -> 320 blocks
    {
        auto k = conv_pad<32, 64, 8, 2, 4, 8, 2, 11, 130, 130, 5, 64, 64,
                          0, 0, 0, 3, 3, 3, 2, 2, 2>;
        size_t smem = (16ull * 27) * 8 * 8;  // 27648 (CI/2=16)
        dim3 grid(1, 2, 8 * 5 * B_ * 2);
        k<<<grid, blk, smem>>>(h2, m2, h3, m3, w3, gg3, b3, rm3, rv3);
        dim3 bgrid((unsigned)((PLANE3 / 4 + 255) / 256), B_ * 64);
        bn_pass<64, PLANE3><<<bgrid, 256>>>(h3, m3, gg3, b3, rm3, rv3);
    }
    // block4: 64->64, k(3,1,1) s(2,1,1), (5,64,64) -> (2,64,64) = d_out
    // COG=8, TW=2, TH=4 (NP=4). grid: y=2 covers oh 0..63 with TH=4
    {
        auto k = conv_pad<64, 64, 8, 2, 4, 8, 1, 5, 64, 64, 2, 64, 64,
                          0, 0, 0, 3, 1, 1, 2, 1, 1>;
        size_t smem = (64ull * 3) * 8 * 8;   // 12288
        dim3 grid(1, 2, 8 * 2 * B_);
        k<<<grid, blk, smem>>>(h3, m3, out, m3, w4, gg4, b4, rm4, rv4);
    }
}

// round 9
// speedup vs baseline: 1.3294x; 1.2825x over previous
#include <cuda_runtime.h>
#include <cuda_bf16.h>

// ---------------------------------------------------------------------------
// SpMiddleFHDLite — sparse block1 + padded dense convs, packed fma.rn.f32x2.
// R4 tile shape (COG=8, NP=2, non-adjacent pairing, float2 kw-overlap loads),
// 128-thread blocks for wave granularity, LDS.128 paired weight loads.
// ---------------------------------------------------------------------------

#define EPS 1e-3f
typedef unsigned long long u64;

static constexpr int B_ = 2;

// h1 padded for block2's pad (1,1,1): (23,258,258)
static constexpr int PD1 = 23, PH1 = 258, PW1 = 258;
static constexpr long long PLANE1 = (long long)PD1 * PH1 * PW1;
// h2 padded for block3's pad (0,1,1): (11,130,130)
static constexpr int PD2 = 11, PH2 = 130, PW2 = 130;
static constexpr long long PLANE2 = (long long)PD2 * PH2 * PW2;
static constexpr long long PLANE3 = 5LL * 64 * 64;   // h3 (no halo)

__device__ __align__(256) float         g_h1[B_ * 16 * PLANE1];
__device__ __align__(256) unsigned char g_m1[B_ * PLANE1 + 16];
__device__ __align__(256) float         g_h2[B_ * 32 * PLANE2];
__device__ __align__(256) unsigned char g_m2[B_ * PLANE2 + 16];
__device__ __align__(256) float         g_h3[B_ * 64 * PLANE3];
__device__ __align__(256) unsigned char g_m3[B_ * PLANE3 + 16];

// ---------------------------------------------------------------------------
__device__ __forceinline__ u64 pk2(float lo, float hi) {
    u64 r;
    unsigned l = __float_as_uint(lo), h = __float_as_uint(hi);
    asm("mov.b64 %0, {%1,%2};" : "=l"(r) : "r"(l), "r"(h));
    return r;
}
__device__ __forceinline__ void upk2(u64 v, float& lo, float& hi) {
    unsigned l, h;
    asm("mov.b64 {%0,%1}, %2;" : "=r"(l), "=r"(h) : "l"(v));
    lo = __uint_as_float(l); hi = __uint_as_float(h);
}
__device__ __forceinline__ void fma2(u64& d, u64 a, u64 b) {
    asm("fma.rn.f32x2 %0, %1, %2, %0;" : "+l"(d) : "l"(a), "l"(b));
}

// ---------------------------------------------------------------------------
// Sparse block1: each thread = (voxel, co). Scatter w.f into h1 accumulator.
// ---------------------------------------------------------------------------
__global__ void __launch_bounds__(256)
scatter_conv1(const float* __restrict__ vf, const int* __restrict__ coors,
              float* __restrict__ h1, unsigned char* __restrict__ m1,
              const float* __restrict__ W, int nv) {
    __shared__ float sw[16 * 3 * 27];
    int tid = threadIdx.x;
    for (int i = tid; i < 16 * 3 * 27; i += 256) sw[i] = W[i];
    __syncthreads();

    int g = blockIdx.x * 256 + tid;
    int vi = g >> 4, co = g & 15;
    if (vi >= nv) return;

    float f0 = vf[3 * vi], f1 = vf[3 * vi + 1], f2 = vf[3 * vi + 2];
    int4 cz = *reinterpret_cast<const int4*>(coors + 4 * vi);
    int b = cz.x, z = cz.y, y = cz.z, x = cz.w;

    int odl[2], kdl[2], nz = 1;
    if (z & 1) { odl[0] = (z - 1) >> 1; kdl[0] = 2; odl[1] = (z + 1) >> 1; kdl[1] = 0;
                 nz = (((z + 1) >> 1) < 21) ? 2 : 1; }
    else       { odl[0] = z >> 1; kdl[0] = 1; }
    int ohl[2], khl[2], ny = 1;
    if (y & 1) { ohl[0] = (y - 1) >> 1; khl[0] = 2; ohl[1] = (y + 1) >> 1; khl[1] = 0;
                 ny = (((y + 1) >> 1) < 256) ? 2 : 1; }
    else       { ohl[0] = y >> 1; khl[0] = 1; }
    int owl[2], kwl[2], nx = 1;
    if (x & 1) { owl[0] = (x - 1) >> 1; kwl[0] = 2; owl[1] = (x + 1) >> 1; kwl[1] = 0;
                 nx = (((x + 1) >> 1) < 256) ? 2 : 1; }
    else       { owl[0] = x >> 1; kwl[0] = 1; }

    const float* wc = &sw[co * 81];
    float* hc = h1 + (size_t)(b * 16 + co) * PLANE1;
    unsigned char* mb = m1 + (size_t)b * PLANE1;

    for (int iz = 0; iz < nz; iz++)
        for (int iy = 0; iy < ny; iy++)
            for (int ix = 0; ix < nx; ix++) {
                int k = (kdl[iz] * 3 + khl[iy]) * 3 + kwl[ix];
                float val = wc[k] * f0 + wc[27 + k] * f1 + wc[54 + k] * f2;
                size_t sp = (size_t)(odl[iz] + 1) * (PH1 * PW1)
                          + (size_t)(ohl[iy] + 1) * PW1 + (owl[ix] + 1);
                atomicAdd(hc + sp, val);
                if (co == 0) mb[sp] = 1;
            }
}

// ---------------------------------------------------------------------------
// BN+ReLU+mask elementwise pass, in place.
// ---------------------------------------------------------------------------
template<int CH, long long PLANE>
__global__ void __launch_bounds__(256)
bn_pass(float* __restrict__ h, const unsigned char* __restrict__ m,
        const float* __restrict__ Ga, const float* __restrict__ Be,
        const float* __restrict__ Rm, const float* __restrict__ Rv) {
    int c = blockIdx.y % CH;
    int b = blockIdx.y / CH;
    float inv = Ga[c] * rsqrtf(Rv[c] + EPS);
    float sh  = Be[c] - Rm[c] * inv;
    size_t p = ((size_t)blockIdx.x * 256 + threadIdx.x) * 4;
    if (p >= (size_t)PLANE) return;
    float4* vp = reinterpret_cast<float4*>(h + (size_t)blockIdx.y * PLANE + p);
    float4 v = *vp;
    uchar4 mm = *reinterpret_cast<const uchar4*>(m + (size_t)b * PLANE + p);
    v.x = mm.x ? fmaxf(fmaf(v.x, inv, sh), 0.f) : 0.f;
    v.y = mm.y ? fmaxf(fmaf(v.y, inv, sh), 0.f) : 0.f;
    v.z = mm.z ? fmaxf(fmaf(v.z, inv, sh), 0.f) : 0.f;
    v.w = mm.w ? fmaxf(fmaf(v.w, inv, sh), 0.f) : 0.f;
    *vp = v;
}

// ---------------------------------------------------------------------------
// Padded dense conv (+ optional fused BN/ReLU/mask), packed f32x2 FMA.
// 32*TW == OW. Thread tile: TW x TH outputs x COG channels (COG even).
// Weights read from smem as ulonglong2 (2 co per LDS.128).
// NSPLIT>1: raw partial sums via atomicAdd (bn applied by later bn_pass).
// KW==3 && SW==2: kw0/kw1 taps share one float2 load.
// ---------------------------------------------------------------------------
template<int CI, int CO, int COG, int TW, int TH, int BY, int NSPLIT,
         int IDP, int IHP, int IWP,
         int OD, int OH, int OW,
         int OPD, int OPH, int OPW,
         int KD, int KH, int KW, int SD, int SH, int SW>
__global__ void __launch_bounds__(32 * BY)
conv_pad(const float* __restrict__ in, const unsigned char* __restrict__ mi,
         float* __restrict__ out, unsigned char* __restrict__ mo,
         const float* __restrict__ Wt, const float* __restrict__ Ga,
         const float* __restrict__ Be, const float* __restrict__ Rm,
         const float* __restrict__ Rv) {
    constexpr int NCOG = CO / COG;
    constexpr int NT = TW * TH;      // even
    constexpr int NP = NT / 2;
    constexpr int NTHR = 32 * BY;
    constexpr int CIL = CI / NSPLIT;
    constexpr int WSTEPS = CIL * KD * KH * KW;
    constexpr int ODP = OD + 2 * OPD, OHP = OH + 2 * OPH, OWP = OW + 2 * OPW;
    constexpr bool KW3S2 = (KW == 3 && SW == 2);
    static_assert(COG % 2 == 0, "COG must be even for paired weight loads");
    extern __shared__ u64 sw2[];

    const int tid = threadIdx.y * 32 + threadIdx.x;
    int zi = blockIdx.z;
    const int cg = zi % NCOG; zi /= NCOG;
    const int od = zi % OD;  zi /= OD;
    const int b  = zi % B_;
    const int sp = zi / B_;          // ci split index
    const int ci0 = sp * CIL;

    for (int i = tid; i < WSTEPS * COG; i += NTHR) {
        int co = i % COG; int r = i / COG;
        int kw = r % KW; r /= KW;
        int kh = r % KH; r /= KH;
        int kd = r % KD; int cil = r / KD;
        float w = Wt[((((cg * COG + co) * CI + ci0 + cil) * KD + kd) * KH + kh) * KW + kw];
        sw2[i] = pk2(w, w);
    }
    __syncthreads();

    const int ow0 = threadIdx.x;                           // + 32*tw
    const int oh0 = (blockIdx.y * BY + threadIdx.y) * TH;  // + th

    unsigned any[NT];
#pragma unroll
    for (int t = 0; t < NT; t++) any[t] = 0;
    if (NSPLIT == 1 || (cg == 0 && sp == 0)) {
        const unsigned char* mb = mi + (size_t)b * IDP * IHP * IWP;
#pragma unroll
        for (int kd = 0; kd < KD; kd++)
#pragma unroll
            for (int kh = 0; kh < KH; kh++)
#pragma unroll
                for (int th = 0; th < TH; th++) {
                    const unsigned char* mrow =
                        mb + ((size_t)(od * SD + kd) * IHP + (oh0 + th) * SH + kh) * IWP;
#pragma unroll
                    for (int kw = 0; kw < KW; kw++)
#pragma unroll
                        for (int tw = 0; tw < TW; tw++)
                            any[th * TW + tw] |= mrow[(ow0 + 32 * tw) * SW + kw];
                }
    }

    u64 acc[COG][NP];
#pragma unroll
    for (int co = 0; co < COG; co++)
#pragma unroll
        for (int p = 0; p < NP; p++) acc[co][p] = 0ull;

    const float* inb = in + ((size_t)b * CI + ci0) * IDP * IHP * IWP;
#pragma unroll 1
    for (int cil = 0; cil < CIL; cil++) {
#pragma unroll
        for (int kd = 0; kd < KD; kd++) {
            const float* pl = inb + ((size_t)cil * IDP + od * SD + kd) * (IHP * IWP);
#pragma unroll
            for (int kh = 0; kh < KH; kh++) {
                const float* row[TH];
#pragma unroll
                for (int th = 0; th < TH; th++)
                    row[th] = pl + ((size_t)(oh0 + th) * SH + kh) * IWP;

                if (KW3S2) {
                    float2 a01[NT]; float a2[NT];
#pragma unroll
                    for (int th = 0; th < TH; th++)
#pragma unroll
                        for (int tw = 0; tw < TW; tw++) {
                            int iw = (ow0 + 32 * tw) * 2;
                            a01[th * TW + tw] =
                                *reinterpret_cast<const float2*>(row[th] + iw);
                            a2[th * TW + tw] = row[th][iw + 2];
                        }
#pragma unroll
                    for (int kw = 0; kw < 3; kw++) {
                        u64 vp[NP];
#pragma unroll
                        for (int p = 0; p < NP; p++) {
                            int t0 = 2 * p, t1 = 2 * p + 1;
                            float v0 = (kw == 0) ? a01[t0].x : (kw == 1) ? a01[t0].y : a2[t0];
                            float v1 = (kw == 0) ? a01[t1].x : (kw == 1) ? a01[t1].y : a2[t1];
                            vp[p] = pk2(v0, v1);
                        }
                        const u64* wp = &sw2[(((cil * KD + kd) * KH + kh) * 3 + kw) * COG];
#pragma unroll
                        for (int co2 = 0; co2 < COG / 2; co2++) {
                            ulonglong2 ww =
                                *reinterpret_cast<const ulonglong2*>(wp + 2 * co2);
#pragma unroll
                            for (int p = 0; p < NP; p++) fma2(acc[2 * co2][p], vp[p], ww.x);
#pragma unroll
                            for (int p = 0; p < NP; p++) fma2(acc[2 * co2 + 1][p], vp[p], ww.y);
                        }
                    }
                } else {
#pragma unroll
                    for (int kw = 0; kw < KW; kw++) {
                        u64 vp[NP];
#pragma unroll
                        for (int p = 0; p < NP; p++) {
                            int t0 = 2 * p, t1 = 2 * p + 1;
                            int th0 = t0 / TW, tw0 = t0 % TW;
                            int th1 = t1 / TW, tw1 = t1 % TW;
                            float v0 = row[th0][(ow0 + 32 * tw0) * SW + kw];
                            float v1 = row[th1][(ow0 + 32 * tw1) * SW + kw];
                            vp[p] = pk2(v0, v1);
                        }
                        const u64* wp = &sw2[(((cil * KD + kd) * KH + kh) * KW + kw) * COG];
#pragma unroll
                        for (int co2 = 0; co2 < COG / 2; co2++) {
                            ulonglong2 ww =
                                *reinterpret_cast<const ulonglong2*>(wp + 2 * co2);
#pragma unroll
                            for (int p = 0; p < NP; p++) fma2(acc[2 * co2][p], vp[p], ww.x);
#pragma unroll
                            for (int p = 0; p < NP; p++) fma2(acc[2 * co2 + 1][p], vp[p], ww.y);
                        }
                    }
                }
            }
        }
    }

    if (NSPLIT > 1) {
#pragma unroll
        for (int co = 0; co < COG; co++) {
            int c = cg * COG + co;
            size_t obc = ((size_t)(b * CO + c) * ODP + od) * ((size_t)OHP * OWP);
#pragma unroll
            for (int p = 0; p < NP; p++) {
                float a0, a1;
                upk2(acc[co][p], a0, a1);
                int t0 = 2 * p, t1 = 2 * p + 1;
                int th0 = t0 / TW, tw0 = t0 % TW;
                int th1 = t1 / TW, tw1 = t1 % TW;
                atomicAdd(&out[obc + (size_t)(oh0 + th0) * OWP + (ow0 + 32 * tw0)], a0);
                atomicAdd(&out[obc + (size_t)(oh0 + th1) * OWP + (ow0 + 32 * tw1)], a1);
            }
        }
        if (cg == 0 && sp == 0) {
            size_t mbc = ((size_t)b * ODP + od) * ((size_t)OHP * OWP);
#pragma unroll
            for (int t = 0; t < NT; t++) {
                int th = t / TW, tw = t % TW;
                mo[mbc + (size_t)(oh0 + th) * OWP + (ow0 + 32 * tw)] = any[t] ? 1 : 0;
            }
        }
    } else {
#pragma unroll
        for (int co = 0; co < COG; co++) {
            int c = cg * COG + co;
            float inv = Ga[c] * rsqrtf(Rv[c] + EPS);
            float sh  = Be[c] - Rm[c] * inv;
            size_t obc = ((size_t)(b * CO + c) * ODP + od + OPD) * ((size_t)OHP * OWP);
#pragma unroll
            for (int p = 0; p < NP; p++) {
                float a0, a1;
                upk2(acc[co][p], a0, a1);
                int t0 = 2 * p, t1 = 2 * p + 1;
                int th0 = t0 / TW, tw0 = t0 % TW;
                int th1 = t1 / TW, tw1 = t1 % TW;
                float v0 = any[t0] ? fmaxf(fmaf(a0, inv, sh), 0.f) : 0.f;
                float v1 = any[t1] ? fmaxf(fmaf(a1, inv, sh), 0.f) : 0.f;
                out[obc + (size_t)(oh0 + th0 + OPH) * OWP + (ow0 + 32 * tw0 + OPW)] = v0;
                out[obc + (size_t)(oh0 + th1 + OPH) * OWP + (ow0 + 32 * tw1 + OPW)] = v1;
            }
        }
        if (cg == 0) {
            size_t mbc = ((size_t)b * ODP + od + OPD) * ((size_t)OHP * OWP);
#pragma unroll
            for (int t = 0; t < NT; t++) {
                int th = t / TW, tw = t % TW;
                mo[mbc + (size_t)(oh0 + th + OPH) * OWP + (ow0 + 32 * tw + OPW)] = any[t] ? 1 : 0;
            }
        }
    }
}

// ---------------------------------------------------------------------------
extern "C" void kernel_launch(void* const* d_in, const int* in_sizes, int n_in,
                              void* d_out, int out_size) {
    const float* vf    = (const float*)d_in[0];
    const int*   coors = (const int*)d_in[1];
    const float *w1 = (const float*)d_in[3],  *gg1 = (const float*)d_in[4],
                *b1 = (const float*)d_in[5],  *rm1 = (const float*)d_in[6],
                *rv1 = (const float*)d_in[7];
    const float *w2 = (const float*)d_in[8],  *gg2 = (const float*)d_in[9],
                *b2 = (const float*)d_in[10], *rm2 = (const float*)d_in[11],
                *rv2 = (const float*)d_in[12];
    const float *w3 = (const float*)d_in[13], *gg3 = (const float*)d_in[14],
                *b3 = (const float*)d_in[15], *rm3 = (const float*)d_in[16],
                *rv3 = (const float*)d_in[17];
    const float *w4 = (const float*)d_in[18], *gg4 = (const float*)d_in[19],
                *b4 = (const float*)d_in[20], *rm4 = (const float*)d_in[21],
                *rv4 = (const float*)d_in[22];
    float* out = (float*)d_out;
    const int nv = in_sizes[0] / 3;

    float *h1, *h2, *h3;
    unsigned char *m1, *m2, *m3;
    cudaGetSymbolAddress((void**)&h1, g_h1);
    cudaGetSymbolAddress((void**)&m1, g_m1);
    cudaGetSymbolAddress((void**)&h2, g_h2);
    cudaGetSymbolAddress((void**)&m2, g_m2);
    cudaGetSymbolAddress((void**)&h3, g_h3);
    cudaGetSymbolAddress((void**)&m3, g_m3);

    cudaMemsetAsync(h1, 0, (size_t)B_ * 16 * PLANE1 * sizeof(float));
    cudaMemsetAsync(m1, 0, (size_t)B_ * PLANE1 + 16);
    cudaMemsetAsync(h2, 0, (size_t)B_ * 32 * PLANE2 * sizeof(float));
    cudaMemsetAsync(m2, 0, (size_t)B_ * PLANE2 + 16);
    cudaMemsetAsync(h3, 0, (size_t)B_ * 64 * PLANE3 * sizeof(float));

    // block1 sparse
    {
        int nthreads = nv * 16;
        scatter_conv1<<<(nthreads + 255) / 256, 256>>>(vf, coors, h1, m1, w1, nv);
        dim3 grid((unsigned)((PLANE1 / 4 + 255) / 256), B_ * 16);
        bn_pass<16, PLANE1><<<grid, 256>>>(h1, m1, gg1, b1, rm1, rv1);
    }

    dim3 blk(32, 4, 1);   // 128-thread blocks

    // block2: 16->32, (23,258,258)pad -> (11,128,128), out halo (0,1,1)
    // COG=8, TW=4, TH=1, BY=4. grid: y=32, z=4*11*2=88 -> 2816 blocks
    {
        auto k = conv_pad<16, 32, 8, 4, 1, 4, 1, 23, 258, 258, 11, 128, 128,
                          0, 1, 1, 3, 3, 3, 2, 2, 2>;
        size_t smem = (16ull * 27) * 8 * 8;  // 27648
        dim3 grid(1, 32, B_ * 11 * 4);
        k<<<grid, blk, smem>>>(h1, m1, h2, m2, w2, gg2, b2, rm2, rv2);
    }
    // block3: 32->64, (11,130,130)pad -> (5,64,64) raw, CI split x2
    // COG=8, TW=2, TH=2, BY=4. grid: y=8, z=8*5*2*2=160 -> 1280 blocks
    {
        auto k = conv_pad<32, 64, 8, 2, 2, 4, 2, 11, 130, 130, 5, 64, 64,
                          0, 0, 0, 3, 3, 3, 2, 2, 2>;
        size_t smem = (16ull * 27) * 8 * 8;  // 27648 (CI/2=16)
        dim3 grid(1, 8, 8 * 5 * B_ * 2);
        k<<<grid, blk, smem>>>(h2, m2, h3, m3, w3, gg3, b3, rm3, rv3);
        dim3 bgrid((unsigned)((PLANE3 / 4 + 255) / 256), B_ * 64);
        bn_pass<64, PLANE3><<<bgrid, 256>>>(h3, m3, gg3, b3, rm3, rv3);
    }
    // block4: 64->64, k(3,1,1) s(2,1,1), (5,64,64) -> (2,64,64) = d_out
    // COG=8, TW=2, TH=2, BY=4. grid: y=8 covers oh 0..63
    {
        auto k = conv_pad<64, 64, 8, 2, 2, 4, 1, 5, 64, 64, 2, 64, 64,
                          0, 0, 0, 3, 1, 1, 2, 1, 1>;
        size_t smem = (64ull * 3) * 8 * 8;   // 12288
        dim3 grid(1, 8, 8 * 2 * B_);
        k<<<grid, blk, smem>>>(h3, m3, out, m3, w4, gg4, b4, rm4, rv4);
    }
}